// round 1
// baseline (speedup 1.0000x reference)
#include <cuda_runtime.h>
#include <math.h>

#define C64 64
#define HW  3136
#define NBATCH 128
#define MTOT 401408            // 128*3136
#define STILES 49              // 3136/64
#define TILES_TOTAL 6272       // 128*49
#define NB1 392
#define TPB1 16                // 392*16 = 6272
#define NB2 784
#define TPB2 8                 // 784*8  = 6272
#define NS_ITERS 6
#define EPSV 1e-3f

// -------- device scratch (no allocations allowed) --------
__device__ float g_partG[NB1][C64 * C64];
__device__ float g_partS[NB1][C64];
__device__ float g_G[C64 * C64];
__device__ float g_S[C64];
__device__ float g_wm[C64 * C64];
__device__ float g_bias[C64];

#define FMA16(a, b)                                                         \
    acc[0][0] += a.x * b.x; acc[0][1] += a.x * b.y;                         \
    acc[0][2] += a.x * b.z; acc[0][3] += a.x * b.w;                         \
    acc[1][0] += a.y * b.x; acc[1][1] += a.y * b.y;                         \
    acc[1][2] += a.y * b.z; acc[1][3] += a.y * b.w;                         \
    acc[2][0] += a.z * b.x; acc[2][1] += a.z * b.y;                         \
    acc[2][2] += a.z * b.z; acc[2][3] += a.z * b.w;                         \
    acc[3][0] += a.w * b.x; acc[3][1] += a.w * b.y;                         \
    acc[3][2] += a.w * b.z; acc[3][3] += a.w * b.w;

// =====================================================================
// Pass 1: per-block partial Gram (64x64) + per-channel partial sums
// =====================================================================
__global__ void __launch_bounds__(256) gram_kernel(const float* __restrict__ X) {
    __shared__ float T[64][68];   // T[pos][ch], padded (stride 272B, 16B-aligned rows)
    __shared__ float ssum[64];

    const int tid = threadIdx.x;
    const int ty = tid >> 4, tx = tid & 15;

    float acc[4][4];
#pragma unroll
    for (int i = 0; i < 4; i++)
#pragma unroll
        for (int j = 0; j < 4; j++) acc[i][j] = 0.f;
    float csum[4] = {0.f, 0.f, 0.f, 0.f};
    if (tid < 64) ssum[tid] = 0.f;

    for (int t = 0; t < TPB1; ++t) {
        const int tileId = blockIdx.x * TPB1 + t;
        const int n = tileId / STILES;
        const int s0 = (tileId - n * STILES) * 64;
        __syncthreads();
        // load 64ch x 64pos tile, transposed into T[pos][ch]
#pragma unroll
        for (int r = 0; r < 4; ++r) {
            const int idx = tid + r * 256;          // 0..1023
            const int c = idx >> 4;                 // channel 0..63 (== ty + 16r)
            const int p = (idx & 15) << 2;          // position 0..60
            const float4 v = *reinterpret_cast<const float4*>(
                X + (size_t)(n * C64 + c) * HW + s0 + p);
            T[p + 0][c] = v.x; T[p + 1][c] = v.y;
            T[p + 2][c] = v.z; T[p + 3][c] = v.w;
            csum[r] += (v.x + v.y) + (v.z + v.w);
        }
        __syncthreads();
#pragma unroll 16
        for (int k = 0; k < 64; ++k) {
            const float4 a = *reinterpret_cast<const float4*>(&T[k][ty << 2]);
            const float4 b = *reinterpret_cast<const float4*>(&T[k][tx << 2]);
            FMA16(a, b)
        }
    }
    __syncthreads();
#pragma unroll
    for (int r = 0; r < 4; ++r) atomicAdd(&ssum[ty + (r << 4)], csum[r]);
    __syncthreads();

    float* pg = g_partG[blockIdx.x];
#pragma unroll
    for (int i = 0; i < 4; i++)
#pragma unroll
        for (int j = 0; j < 4; j++)
            pg[(ty * 4 + i) * C64 + tx * 4 + j] = acc[i][j];
    if (tid < 64) g_partS[blockIdx.x][tid] = ssum[tid];
}

// =====================================================================
// Pass 1.5: reduce partials (fixed order -> deterministic)
// =====================================================================
__global__ void __launch_bounds__(256) reduce_kernel() {
    if (blockIdx.x < 16) {
        const int e = blockIdx.x * 256 + threadIdx.x;   // 0..4095
        float a = 0.f;
        for (int b = 0; b < NB1; ++b) a += g_partG[b][e];
        g_G[e] = a;
    } else {
        if (threadIdx.x < 64) {
            float a = 0.f;
            for (int b = 0; b < NB1; ++b) a += g_partS[b][threadIdx.x];
            g_S[threadIdx.x] = a;
        }
    }
}

// =====================================================================
// Pass 2: single-block solve: sigma -> Newton-Schulz inverse sqrt -> wm
//   sigma = G/m - mu mu^T + eps I     (symmetric, bitwise)
//   An = sigma / ||sigma||_inf  (spectrum in (0,1] -> NS always converges)
//   Z_{k+1} = 1.5 Z - 0.5 * An * Z^3 ;  wm = Z * sqrt(1/||sigma||_inf)^-... = Z*sqrt(r)
//   matmuls read operands as P^T Q via row LDS.128 — valid since all symmetric.
// =====================================================================
__device__ __forceinline__ void mm64(const float (*P)[68], const float (*Q)[68],
                                     float (*Cm)[68], int ty, int tx) {
    float acc[4][4];
#pragma unroll
    for (int i = 0; i < 4; i++)
#pragma unroll
        for (int j = 0; j < 4; j++) acc[i][j] = 0.f;
#pragma unroll 16
    for (int k = 0; k < 64; ++k) {
        const float4 a = *reinterpret_cast<const float4*>(&P[k][ty << 2]);
        const float4 b = *reinterpret_cast<const float4*>(&Q[k][tx << 2]);
        FMA16(a, b)
    }
#pragma unroll
    for (int i = 0; i < 4; i++)
#pragma unroll
        for (int j = 0; j < 4; j++)
            Cm[ty * 4 + i][tx * 4 + j] = acc[i][j];
}

__global__ void __launch_bounds__(256) solve_kernel() {
    extern __shared__ float sm[];
    float (*An)[68] = (float(*)[68])sm;
    float (*Z)[68]  = (float(*)[68])(sm + 1 * 64 * 68);
    float (*B1)[68] = (float(*)[68])(sm + 2 * 64 * 68);
    float (*B2)[68] = (float(*)[68])(sm + 3 * 64 * 68);
    __shared__ float rowsum[64];
    __shared__ float rinv;

    const int tid = threadIdx.x;
    const int ty = tid >> 4, tx = tid & 15;
    const float invm = 1.f / (float)MTOT;

    for (int e = tid; e < 4096; e += 256) {
        const int i = e >> 6, j = e & 63;
        float s = g_G[e] * invm - (g_S[i] * invm) * (g_S[j] * invm);
        if (i == j) s += EPSV;
        An[i][j] = s;
        Z[i][j] = (i == j) ? 1.f : 0.f;
    }
    __syncthreads();
    if (tid < 64) {
        float rs = 0.f;
        for (int j = 0; j < 64; ++j) rs += fabsf(An[tid][j]);
        rowsum[tid] = rs;
    }
    __syncthreads();
    if (tid == 0) {
        float mx = 0.f;
        for (int i = 0; i < 64; ++i) mx = fmaxf(mx, rowsum[i]);
        rinv = 1.f / mx;
    }
    __syncthreads();
    const float r = rinv;
    for (int e = tid; e < 4096; e += 256) An[e >> 6][e & 63] *= r;
    __syncthreads();

    for (int it = 0; it < NS_ITERS; ++it) {
        mm64(Z, Z, B1, ty, tx);     // B1 = Z^2
        __syncthreads();
        mm64(B1, Z, B2, ty, tx);    // B2 = Z^3
        __syncthreads();
        {   // Z = 1.5 Z - 0.5 * An * B2
            float acc[4][4];
#pragma unroll
            for (int i = 0; i < 4; i++)
#pragma unroll
                for (int j = 0; j < 4; j++) acc[i][j] = 0.f;
#pragma unroll 16
            for (int k = 0; k < 64; ++k) {
                const float4 a = *reinterpret_cast<const float4*>(&An[k][ty << 2]);
                const float4 b = *reinterpret_cast<const float4*>(&B2[k][tx << 2]);
                FMA16(a, b)
            }
#pragma unroll
            for (int i = 0; i < 4; i++)
#pragma unroll
                for (int j = 0; j < 4; j++) {
                    const int ii = ty * 4 + i, jj = tx * 4 + j;
                    Z[ii][jj] = 1.5f * Z[ii][jj] - 0.5f * acc[i][j];
                }
        }
        __syncthreads();
    }

    const float sr = sqrtf(r);
    for (int e = tid; e < 4096; e += 256) g_wm[e] = Z[e >> 6][e & 63] * sr;
    __syncthreads();
    if (tid < 64) {
        float b = 0.f;
        for (int k = 0; k < 64; ++k) b += Z[tid][k] * g_S[k];
        g_bias[tid] = b * sr * invm;   // wm @ mean
    }
}

// =====================================================================
// Pass 3: out[c][s] = sum_k wm[c][k] * x[k][s] - bias[c]
// (wm is symmetric -> read rows of wm for column access)
// =====================================================================
__global__ void __launch_bounds__(256) apply_kernel(const float* __restrict__ X,
                                                    float* __restrict__ Y) {
    __shared__ float Wm[64][68];
    __shared__ float Xs[64][68];   // Xs[ch][pos], natural layout
    __shared__ float bs[64];

    const int tid = threadIdx.x;
    const int ty = tid >> 4, tx = tid & 15;

    for (int e = tid; e < 4096; e += 256) Wm[e >> 6][e & 63] = g_wm[e];
    if (tid < 64) bs[tid] = g_bias[tid];

    for (int t = 0; t < TPB2; ++t) {
        const int tileId = blockIdx.x * TPB2 + t;
        const int n = tileId / STILES;
        const int s0 = (tileId - n * STILES) * 64;
        __syncthreads();
#pragma unroll
        for (int r = 0; r < 4; ++r) {
            const int idx = tid + r * 256;
            const int c = idx >> 4;
            const int p = (idx & 15) << 2;
            *reinterpret_cast<float4*>(&Xs[c][p]) =
                *reinterpret_cast<const float4*>(X + (size_t)(n * C64 + c) * HW + s0 + p);
        }
        __syncthreads();
        float acc[4][4];
#pragma unroll
        for (int i = 0; i < 4; i++)
#pragma unroll
            for (int j = 0; j < 4; j++) acc[i][j] = 0.f;
#pragma unroll 16
        for (int k = 0; k < 64; ++k) {
            const float4 a = *reinterpret_cast<const float4*>(&Wm[k][ty << 2]); // wm[k][c..] == wm[c..][k]
            const float4 b = *reinterpret_cast<const float4*>(&Xs[k][tx << 2]);
            FMA16(a, b)
        }
#pragma unroll
        for (int i = 0; i < 4; i++) {
            const int c = ty * 4 + i;
            const float bb = bs[c];
            const float4 o = make_float4(acc[i][0] - bb, acc[i][1] - bb,
                                         acc[i][2] - bb, acc[i][3] - bb);
            *reinterpret_cast<float4*>(Y + (size_t)(n * C64 + c) * HW + s0 + (tx << 2)) = o;
        }
    }
}

// =====================================================================
extern "C" void kernel_launch(void* const* d_in, const int* in_sizes, int n_in,
                              void* d_out, int out_size) {
    const float* X = (const float*)d_in[0];
    float* Y = (float*)d_out;

    cudaFuncSetAttribute(solve_kernel, cudaFuncAttributeMaxDynamicSharedMemorySize,
                         4 * 64 * 68 * (int)sizeof(float));

    gram_kernel<<<NB1, 256>>>(X);
    reduce_kernel<<<17, 256>>>();
    solve_kernel<<<1, 256, 4 * 64 * 68 * sizeof(float)>>>();
    apply_kernel<<<NB2, 256>>>(X, Y);
}

// round 2
// speedup vs baseline: 1.0004x; 1.0004x over previous
#include <cuda_runtime.h>
#include <stdint.h>
#include <math.h>

#define C64 64
#define HW  3136
#define MTOT 401408            // 128*3136
#define STILES 49              // 3136/64
#define NB1 1568
#define TPB1 4                 // 1568*4 = 6272 tiles
#define NB2 1568
#define TPB2 4
#define NS_ITERS 5
#define EPSV 1e-3f

// -------- device scratch (no allocations allowed) --------
__device__ float g_partG[NB1][C64 * C64];
__device__ float g_partS[NB1][C64];
__device__ float g_G[C64 * C64];
__device__ float g_S[C64];
__device__ float g_wm[C64 * C64];
__device__ float g_bias[C64];

__device__ __forceinline__ void cpasync16(uint32_t dst, const void* src) {
    asm volatile("cp.async.cg.shared.global [%0], [%1], 16;\n" :: "r"(dst), "l"(src));
}
__device__ __forceinline__ void cp_commit() {
    asm volatile("cp.async.commit_group;\n" ::: "memory");
}
__device__ __forceinline__ void cp_wait1() {
    asm volatile("cp.async.wait_group 1;\n" ::: "memory");
}

// =====================================================================
// Pass 1: partial Gram. 128 threads, 8x4 per-thread tile, double-buffered,
// shuffle-based 4x4 transpose -> conflict-free STS.128.
// =====================================================================
__device__ __forceinline__ void gram_load(const float* __restrict__ X, int tileId,
                                          int cbase, int q, float4* v, float* csum) {
    const int n = tileId / STILES;
    const int s0 = (tileId - n * STILES) * 64;
    const float* p = X + (size_t)(n * C64 + cbase) * HW + s0 + 4 * q;
#pragma unroll
    for (int r = 0; r < 8; ++r) {
        v[r] = *reinterpret_cast<const float4*>(p + (size_t)(8 * r) * HW);
        csum[r] += (v[r].x + v[r].y) + (v[r].z + v[r].w);
    }
}

__device__ __forceinline__ void gram_store(float (*Tb)[68], const float4* v,
                                           int l2, int q, int cg) {
#pragma unroll
    for (int r = 0; r < 8; ++r) {
        float4 t = v[r];
        float a, b;
        // 4x4 transpose across the 4 lanes of a quad (2 butterfly phases)
        a = (l2 & 1) ? t.x : t.y;  b = (l2 & 1) ? t.z : t.w;
        a = __shfl_xor_sync(0xffffffffu, a, 1);
        b = __shfl_xor_sync(0xffffffffu, b, 1);
        if (l2 & 1) { t.x = a; t.z = b; } else { t.y = a; t.w = b; }
        a = (l2 & 2) ? t.x : t.z;  b = (l2 & 2) ? t.y : t.w;
        a = __shfl_xor_sync(0xffffffffu, a, 2);
        b = __shfl_xor_sync(0xffffffffu, b, 2);
        if (l2 & 2) { t.x = a; t.y = b; } else { t.z = a; t.w = b; }
        // now t = x[8r+4cg+0..3][4q+l2]
        *reinterpret_cast<float4*>(&Tb[4 * q + l2][8 * r + 4 * cg]) = t;
    }
}

__device__ __forceinline__ void gemm_acc(const float (*A)[68], const float (*B)[68],
                                         float acc[8][4], int ty, int tx) {
#pragma unroll 8
    for (int k = 0; k < 64; ++k) {
        const float4 a0 = *reinterpret_cast<const float4*>(&A[k][ty * 8]);
        const float4 a1 = *reinterpret_cast<const float4*>(&A[k][ty * 8 + 4]);
        const float4 b  = *reinterpret_cast<const float4*>(&B[k][tx * 4]);
        const float av[8] = {a0.x, a0.y, a0.z, a0.w, a1.x, a1.y, a1.z, a1.w};
        const float bv[4] = {b.x, b.y, b.z, b.w};
#pragma unroll
        for (int i = 0; i < 8; ++i)
#pragma unroll
            for (int j = 0; j < 4; ++j) acc[i][j] += av[i] * bv[j];
    }
}

__global__ void __launch_bounds__(128) gram_kernel(const float* __restrict__ X) {
    __shared__ float T[2][64][68];
    __shared__ float ssum[64];

    const int tid = threadIdx.x;
    const int l2 = tid & 3;
    const int q  = (tid >> 2) & 15;
    const int cg = (tid >> 6) & 1;
    const int ty = tid >> 4;        // 0..7
    const int tx = tid & 15;
    const int cbase = 4 * cg + l2;

    float acc[8][4];
#pragma unroll
    for (int i = 0; i < 8; ++i)
#pragma unroll
        for (int j = 0; j < 4; ++j) acc[i][j] = 0.f;
    float csum[8] = {0.f, 0.f, 0.f, 0.f, 0.f, 0.f, 0.f, 0.f};
    if (tid < 64) ssum[tid] = 0.f;

    const int tile0 = blockIdx.x * TPB1;

    {   // prologue
        float4 v[8];
        gram_load(X, tile0, cbase, q, v, csum);
        gram_store(T[0], v, l2, q, cg);
    }
    __syncthreads();

#pragma unroll 1
    for (int t = 0; t < TPB1; ++t) {
        float4 nv[8];
        const bool more = (t + 1 < TPB1);
        if (more) gram_load(X, tile0 + t + 1, cbase, q, nv, csum);
        gemm_acc(T[t & 1], T[t & 1], acc, ty, tx);
        if (more) gram_store(T[(t + 1) & 1], nv, l2, q, cg);
        __syncthreads();
    }

#pragma unroll
    for (int r = 0; r < 8; ++r) atomicAdd(&ssum[8 * r + cbase], csum[r]);
    __syncthreads();

    float* pg = g_partG[blockIdx.x];
#pragma unroll
    for (int i = 0; i < 8; ++i)
        *reinterpret_cast<float4*>(&pg[(ty * 8 + i) * C64 + tx * 4]) =
            make_float4(acc[i][0], acc[i][1], acc[i][2], acc[i][3]);
    if (tid < 64) g_partS[blockIdx.x][tid] = ssum[tid];
}

// =====================================================================
// Pass 1.5: reduce partials (fixed order -> deterministic)
// blocks 0..127: G (8 float4-entries each, 16 b-chunks combined in order)
// block 128: S
// =====================================================================
__global__ void __launch_bounds__(128) reduce_kernel() {
    const int tid = threadIdx.x;
    if (blockIdx.x < 128) {
        __shared__ float4 s[16][8];
        const int lane = tid & 7;
        const int bq = tid >> 3;                 // 0..15
        const int e4 = blockIdx.x * 8 + lane;    // float4 index 0..1023
        const float4* pg = reinterpret_cast<const float4*>(g_partG);
        float4 a = make_float4(0.f, 0.f, 0.f, 0.f);
        const int b0 = bq * (NB1 / 16);
#pragma unroll 4
        for (int b = 0; b < NB1 / 16; ++b) {
            const float4 t = pg[(size_t)(b0 + b) * 1024 + e4];
            a.x += t.x; a.y += t.y; a.z += t.z; a.w += t.w;
        }
        s[bq][lane] = a;
        __syncthreads();
        if (tid < 8) {
            float4 r = make_float4(0.f, 0.f, 0.f, 0.f);
            for (int i = 0; i < 16; ++i) {
                const float4 t = s[i][tid];
                r.x += t.x; r.y += t.y; r.z += t.z; r.w += t.w;
            }
            reinterpret_cast<float4*>(g_G)[blockIdx.x * 8 + tid] = r;
        }
    } else {
        __shared__ float s2[2][64];
        const int ch = tid & 63, half = tid >> 6;
        float a = 0.f;
        const int b0 = half * (NB1 / 2);
#pragma unroll 4
        for (int b = 0; b < NB1 / 2; ++b) a += g_partS[b0 + b][ch];
        s2[half][ch] = a;
        __syncthreads();
        if (tid < 64) g_S[tid] = s2[0][tid] + s2[1][tid];
    }
}

// =====================================================================
// Pass 2: single-block solve (Newton-Schulz inverse sqrt), 256 threads
// =====================================================================
#define FMA16(a, b)                                                         \
    acc[0][0] += a.x * b.x; acc[0][1] += a.x * b.y;                         \
    acc[0][2] += a.x * b.z; acc[0][3] += a.x * b.w;                         \
    acc[1][0] += a.y * b.x; acc[1][1] += a.y * b.y;                         \
    acc[1][2] += a.y * b.z; acc[1][3] += a.y * b.w;                         \
    acc[2][0] += a.z * b.x; acc[2][1] += a.z * b.y;                         \
    acc[2][2] += a.z * b.z; acc[2][3] += a.z * b.w;                         \
    acc[3][0] += a.w * b.x; acc[3][1] += a.w * b.y;                         \
    acc[3][2] += a.w * b.z; acc[3][3] += a.w * b.w;

__device__ __forceinline__ void mm64(const float (*P)[68], const float (*Q)[68],
                                     float (*Cm)[68], int ty, int tx) {
    float acc[4][4];
#pragma unroll
    for (int i = 0; i < 4; i++)
#pragma unroll
        for (int j = 0; j < 4; j++) acc[i][j] = 0.f;
#pragma unroll 16
    for (int k = 0; k < 64; ++k) {
        const float4 a = *reinterpret_cast<const float4*>(&P[k][ty << 2]);
        const float4 b = *reinterpret_cast<const float4*>(&Q[k][tx << 2]);
        FMA16(a, b)
    }
#pragma unroll
    for (int i = 0; i < 4; i++)
#pragma unroll
        for (int j = 0; j < 4; j++)
            Cm[ty * 4 + i][tx * 4 + j] = acc[i][j];
}

__global__ void __launch_bounds__(256) solve_kernel() {
    extern __shared__ float sm[];
    float (*An)[68] = (float(*)[68])sm;
    float (*Z)[68]  = (float(*)[68])(sm + 1 * 64 * 68);
    float (*B1)[68] = (float(*)[68])(sm + 2 * 64 * 68);
    float (*B2)[68] = (float(*)[68])(sm + 3 * 64 * 68);
    __shared__ float rowsum[64];
    __shared__ float rinv;

    const int tid = threadIdx.x;
    const int ty = tid >> 4, tx = tid & 15;
    const float invm = 1.f / (float)MTOT;

    for (int e = tid; e < 4096; e += 256) {
        const int i = e >> 6, j = e & 63;
        float s = g_G[e] * invm - (g_S[i] * invm) * (g_S[j] * invm);
        if (i == j) s += EPSV;
        An[i][j] = s;
        Z[i][j] = (i == j) ? 1.f : 0.f;
    }
    __syncthreads();
    if (tid < 64) {
        float rs = 0.f;
        for (int j = 0; j < 64; ++j) rs += fabsf(An[tid][j]);
        rowsum[tid] = rs;
    }
    __syncthreads();
    if (tid == 0) {
        float mx = 0.f;
        for (int i = 0; i < 64; ++i) mx = fmaxf(mx, rowsum[i]);
        rinv = 1.f / mx;
    }
    __syncthreads();
    const float r = rinv;
    for (int e = tid; e < 4096; e += 256) An[e >> 6][e & 63] *= r;
    __syncthreads();

    for (int it = 0; it < NS_ITERS; ++it) {
        mm64(Z, Z, B1, ty, tx);     // B1 = Z^2
        __syncthreads();
        mm64(B1, Z, B2, ty, tx);    // B2 = Z^3
        __syncthreads();
        {   // Z = 1.5 Z - 0.5 * An * B2
            float acc[4][4];
#pragma unroll
            for (int i = 0; i < 4; i++)
#pragma unroll
                for (int j = 0; j < 4; j++) acc[i][j] = 0.f;
#pragma unroll 16
            for (int k = 0; k < 64; ++k) {
                const float4 a = *reinterpret_cast<const float4*>(&An[k][ty << 2]);
                const float4 b = *reinterpret_cast<const float4*>(&B2[k][tx << 2]);
                FMA16(a, b)
            }
#pragma unroll
            for (int i = 0; i < 4; i++)
#pragma unroll
                for (int j = 0; j < 4; j++) {
                    const int ii = ty * 4 + i, jj = tx * 4 + j;
                    Z[ii][jj] = 1.5f * Z[ii][jj] - 0.5f * acc[i][j];
                }
        }
        __syncthreads();
    }

    const float sr = sqrtf(r);
    for (int e = tid; e < 4096; e += 256) g_wm[e] = Z[e >> 6][e & 63] * sr;
    __syncthreads();
    if (tid < 64) {
        float b = 0.f;
        for (int k = 0; k < 64; ++k) b += Z[tid][k] * g_S[k];
        g_bias[tid] = b * sr * invm;   // wm @ mean
    }
}

// =====================================================================
// Pass 3: apply. 128 threads, 8x4 tile, cp.async 2-stage pipeline.
// dynamic smem: Wm[64][68] | Xs0[64][68] | Xs1[64][68] | bs[64]
// =====================================================================
__device__ __forceinline__ void apply_issue(const float* __restrict__ X, int tile,
                                            float (*buf)[68], int tid) {
    const int n = tile / STILES;
    const int s0 = (tile - n * STILES) * 64;
#pragma unroll
    for (int r = 0; r < 8; ++r) {
        const int idx = tid + r * 128;
        const int c = idx >> 4, p = (idx & 15) << 2;
        cpasync16((uint32_t)__cvta_generic_to_shared(&buf[c][p]),
                  X + (size_t)(n * C64 + c) * HW + s0 + p);
    }
    cp_commit();
}

__global__ void __launch_bounds__(128) apply_kernel(const float* __restrict__ X,
                                                    float* __restrict__ Y) {
    extern __shared__ float sm[];
    float (*Wm)[68]  = (float(*)[68])sm;
    float (*Xs0)[68] = (float(*)[68])(sm + 4352);
    float (*Xs1)[68] = (float(*)[68])(sm + 2 * 4352);
    float* bs = sm + 3 * 4352;

    const int tid = threadIdx.x;
    const int ty = tid >> 4, tx = tid & 15;

    const float4* gw = reinterpret_cast<const float4*>(g_wm);
#pragma unroll
    for (int i = 0; i < 8; ++i) {
        const int idx4 = tid + i * 128;            // 0..1023
        const int rr = idx4 >> 4, cc = (idx4 & 15) << 2;
        *reinterpret_cast<float4*>(&Wm[rr][cc]) = gw[idx4];
    }
    if (tid < 64) bs[tid] = g_bias[tid];

    const int tile0 = blockIdx.x * TPB2;
    apply_issue(X, tile0 + 0, Xs0, tid);
    apply_issue(X, tile0 + 1, Xs1, tid);

#pragma unroll 1
    for (int t = 0; t < TPB2; ++t) {
        cp_wait1();
        __syncthreads();
        float (*Xb)[68] = (t & 1) ? Xs1 : Xs0;

        float acc[8][4];
#pragma unroll
        for (int i = 0; i < 8; ++i)
#pragma unroll
            for (int j = 0; j < 4; ++j) acc[i][j] = 0.f;
        // out[c][s] = sum_k wm[c][k] x[k][s]; wm symmetric -> Wm[k][c]
        gemm_acc(Wm, Xb, acc, ty, tx);

        const int tile = tile0 + t;
        const int n = tile / STILES;
        const int s0 = (tile - n * STILES) * 64;
#pragma unroll
        for (int i = 0; i < 8; ++i) {
            const int c = ty * 8 + i;
            const float bb = bs[c];
            *reinterpret_cast<float4*>(Y + (size_t)(n * C64 + c) * HW + s0 + tx * 4) =
                make_float4(acc[i][0] - bb, acc[i][1] - bb, acc[i][2] - bb, acc[i][3] - bb);
        }
        __syncthreads();
        if (t + 2 < TPB2) apply_issue(X, tile0 + t + 2, Xb, tid);
        else cp_commit();   // empty group keeps wait_group<1> semantics valid
    }
}

// =====================================================================
extern "C" void kernel_launch(void* const* d_in, const int* in_sizes, int n_in,
                              void* d_out, int out_size) {
    const float* X = (const float*)d_in[0];
    float* Y = (float*)d_out;

    cudaFuncSetAttribute(solve_kernel, cudaFuncAttributeMaxDynamicSharedMemorySize,
                         4 * 64 * 68 * (int)sizeof(float));
    cudaFuncSetAttribute(apply_kernel, cudaFuncAttributeMaxDynamicSharedMemorySize,
                         (3 * 4352 + 64) * (int)sizeof(float));

    gram_kernel<<<NB1, 128>>>(X);
    reduce_kernel<<<129, 128>>>();
    solve_kernel<<<1, 256, 4 * 64 * 68 * sizeof(float)>>>();
    apply_kernel<<<NB2, 128, (3 * 4352 + 64) * sizeof(float)>>>(X, Y);
}

// round 4
// speedup vs baseline: 1.2301x; 1.2296x over previous
#include <cuda_runtime.h>
#include <stdint.h>
#include <math.h>

#define C64 64
#define HW  3136
#define MTOT 401408            // 128*3136
#define STILES 49              // 3136/64
#define NB1 784
#define TPB1 8                 // 784*8 = 6272 tiles
#define NB2 1568
#define TPB2 4
#define NS_ITERS 4
#define EPSV 1e-3f

// -------- device scratch (no allocations allowed) --------
__device__ float g_partG[NB1][C64 * C64];
__device__ float g_partS[NB1][C64];
__device__ float g_G[C64 * C64];
__device__ float g_S[C64];
__device__ float g_wm[C64 * C64];
__device__ float g_bias[C64];

// -------- packed f32x2 helpers --------
__device__ __forceinline__ uint64_t pack2(float v) {
    uint64_t r; asm("mov.b64 %0, {%1, %1};" : "=l"(r) : "f"(v)); return r;
}
__device__ __forceinline__ void ffma2(uint64_t& d, uint64_t a, uint64_t b) {
    asm("fma.rn.f32x2 %0, %1, %2, %0;" : "+l"(d) : "l"(a), "l"(b));
}
__device__ __forceinline__ float2 unpack2(uint64_t v) {
    float2 f; asm("mov.b64 {%0, %1}, %2;" : "=f"(f.x), "=f"(f.y) : "l"(v)); return f;
}

__device__ __forceinline__ void cpasync16(uint32_t dst, const void* src) {
    asm volatile("cp.async.cg.shared.global [%0], [%1], 16;\n" :: "r"(dst), "l"(src));
}
__device__ __forceinline__ void cp_commit() {
    asm volatile("cp.async.commit_group;\n" ::: "memory");
}
__device__ __forceinline__ void cp_wait1() {
    asm volatile("cp.async.wait_group 1;\n" ::: "memory");
}

// 8x4 per-thread tile as 4 row-pairs x 4 cols of f32x2
__device__ __forceinline__ void gemm_acc2(const float (*A)[68], const float (*B)[68],
                                          uint64_t acc[4][4], int ty, int tx) {
#pragma unroll 8
    for (int k = 0; k < 64; ++k) {
        const ulonglong2 a01 = *reinterpret_cast<const ulonglong2*>(&A[k][ty * 8]);
        const ulonglong2 a23 = *reinterpret_cast<const ulonglong2*>(&A[k][ty * 8 + 4]);
        const float4 b = *reinterpret_cast<const float4*>(&B[k][tx * 4]);
        const uint64_t ap[4] = {a01.x, a01.y, a23.x, a23.y};
        const uint64_t bd[4] = {pack2(b.x), pack2(b.y), pack2(b.z), pack2(b.w)};
#pragma unroll
        for (int i = 0; i < 4; ++i)
#pragma unroll
            for (int j = 0; j < 4; ++j) ffma2(acc[i][j], ap[i], bd[j]);
    }
}

// =====================================================================
// Pass 1: partial Gram. 128 threads, 8x4 tile, double-buffered,
// shuffle-based 4x4 transpose -> conflict-free STS.128.
// =====================================================================
__device__ __forceinline__ void gram_load(const float* __restrict__ X, int tileId,
                                          int cbase, int q, float4* v, float* csum) {
    const int n = tileId / STILES;
    const int s0 = (tileId - n * STILES) * 64;
    const float* p = X + (size_t)(n * C64 + cbase) * HW + s0 + 4 * q;
#pragma unroll
    for (int r = 0; r < 8; ++r) {
        v[r] = *reinterpret_cast<const float4*>(p + (size_t)(8 * r) * HW);
        csum[r] += (v[r].x + v[r].y) + (v[r].z + v[r].w);
    }
}

__device__ __forceinline__ void gram_store(float (*Tb)[68], const float4* v,
                                           int l2, int q, int cg) {
#pragma unroll
    for (int r = 0; r < 8; ++r) {
        float4 t = v[r];
        float a, b;
        a = (l2 & 1) ? t.x : t.y;  b = (l2 & 1) ? t.z : t.w;
        a = __shfl_xor_sync(0xffffffffu, a, 1);
        b = __shfl_xor_sync(0xffffffffu, b, 1);
        if (l2 & 1) { t.x = a; t.z = b; } else { t.y = a; t.w = b; }
        a = (l2 & 2) ? t.x : t.z;  b = (l2 & 2) ? t.y : t.w;
        a = __shfl_xor_sync(0xffffffffu, a, 2);
        b = __shfl_xor_sync(0xffffffffu, b, 2);
        if (l2 & 2) { t.x = a; t.y = b; } else { t.z = a; t.w = b; }
        *reinterpret_cast<float4*>(&Tb[4 * q + l2][8 * r + 4 * cg]) = t;
    }
}

__global__ void __launch_bounds__(128) gram_kernel(const float* __restrict__ X) {
    __shared__ float T[2][64][68];
    __shared__ float ssum[64];

    const int tid = threadIdx.x;
    const int l2 = tid & 3;
    const int q  = (tid >> 2) & 15;
    const int cg = (tid >> 6) & 1;
    const int ty = tid >> 4;        // 0..7
    const int tx = tid & 15;
    const int cbase = 4 * cg + l2;

    uint64_t acc[4][4];
#pragma unroll
    for (int i = 0; i < 4; ++i)
#pragma unroll
        for (int j = 0; j < 4; ++j) acc[i][j] = 0ull;
    float csum[8] = {0.f, 0.f, 0.f, 0.f, 0.f, 0.f, 0.f, 0.f};
    if (tid < 64) ssum[tid] = 0.f;

    const int tile0 = blockIdx.x * TPB1;

    {   // prologue
        float4 v[8];
        gram_load(X, tile0, cbase, q, v, csum);
        gram_store(T[0], v, l2, q, cg);
    }
    __syncthreads();

#pragma unroll 1
    for (int t = 0; t < TPB1; ++t) {
        float4 nv[8];
        const bool more = (t + 1 < TPB1);
        if (more) gram_load(X, tile0 + t + 1, cbase, q, nv, csum);
        gemm_acc2(T[t & 1], T[t & 1], acc, ty, tx);
        if (more) gram_store(T[(t + 1) & 1], nv, l2, q, cg);
        __syncthreads();
    }

#pragma unroll
    for (int r = 0; r < 8; ++r) atomicAdd(&ssum[8 * r + cbase], csum[r]);
    __syncthreads();

    float* pg = g_partG[blockIdx.x];
#pragma unroll
    for (int i = 0; i < 4; ++i) {
        const float2 u0 = unpack2(acc[i][0]);
        const float2 u1 = unpack2(acc[i][1]);
        const float2 u2 = unpack2(acc[i][2]);
        const float2 u3 = unpack2(acc[i][3]);
        const int rowA = ty * 8 + 2 * i, rowB = rowA + 1;
        *reinterpret_cast<float4*>(&pg[rowA * C64 + tx * 4]) =
            make_float4(u0.x, u1.x, u2.x, u3.x);
        *reinterpret_cast<float4*>(&pg[rowB * C64 + tx * 4]) =
            make_float4(u0.y, u1.y, u2.y, u3.y);
    }
    if (tid < 64) g_partS[blockIdx.x][tid] = ssum[tid];
}

// =====================================================================
// Pass 1.5: reduce partials (fixed order -> deterministic)
// =====================================================================
__global__ void __launch_bounds__(128) reduce_kernel() {
    const int tid = threadIdx.x;
    if (blockIdx.x < 128) {
        __shared__ float4 s[16][8];
        const int lane = tid & 7;
        const int bq = tid >> 3;                 // 0..15
        const int e4 = blockIdx.x * 8 + lane;    // float4 index 0..1023
        const float4* pg = reinterpret_cast<const float4*>(g_partG);
        float4 a = make_float4(0.f, 0.f, 0.f, 0.f);
        const int b0 = bq * (NB1 / 16);
#pragma unroll 7
        for (int b = 0; b < NB1 / 16; ++b) {
            const float4 t = pg[(size_t)(b0 + b) * 1024 + e4];
            a.x += t.x; a.y += t.y; a.z += t.z; a.w += t.w;
        }
        s[bq][lane] = a;
        __syncthreads();
        if (tid < 8) {
            float4 r = make_float4(0.f, 0.f, 0.f, 0.f);
            for (int i = 0; i < 16; ++i) {
                const float4 t = s[i][tid];
                r.x += t.x; r.y += t.y; r.z += t.z; r.w += t.w;
            }
            reinterpret_cast<float4*>(g_G)[blockIdx.x * 8 + tid] = r;
        }
    } else {
        __shared__ float s2[2][64];
        const int ch = tid & 63, half = tid >> 6;
        float a = 0.f;
        const int b0 = half * (NB1 / 2);
#pragma unroll 4
        for (int b = 0; b < NB1 / 2; ++b) a += g_partS[b0 + b][ch];
        s2[half][ch] = a;
        __syncthreads();
        if (tid < 64) g_S[tid] = s2[0][tid] + s2[1][tid];
    }
}

// =====================================================================
// Pass 2: single-block solve (Newton-Schulz inverse sqrt), 256 threads
// 4x4 per-thread tile -> 2 row-pairs x 4 cols of f32x2
// =====================================================================
__device__ __forceinline__ void mm64_2(const float (*P)[68], const float (*Q)[68],
                                       float (*Cm)[68], int ty, int tx) {
    uint64_t acc[2][4];
#pragma unroll
    for (int i = 0; i < 2; ++i)
#pragma unroll
        for (int j = 0; j < 4; ++j) acc[i][j] = 0ull;
#pragma unroll 8
    for (int k = 0; k < 64; ++k) {
        const ulonglong2 a = *reinterpret_cast<const ulonglong2*>(&P[k][ty * 4]);
        const float4 b = *reinterpret_cast<const float4*>(&Q[k][tx * 4]);
        const uint64_t bd[4] = {pack2(b.x), pack2(b.y), pack2(b.z), pack2(b.w)};
#pragma unroll
        for (int j = 0; j < 4; ++j) { ffma2(acc[0][j], a.x, bd[j]); ffma2(acc[1][j], a.y, bd[j]); }
    }
#pragma unroll
    for (int i = 0; i < 2; ++i) {
        const float2 u0 = unpack2(acc[i][0]);
        const float2 u1 = unpack2(acc[i][1]);
        const float2 u2 = unpack2(acc[i][2]);
        const float2 u3 = unpack2(acc[i][3]);
        const int rowA = ty * 4 + 2 * i, rowB = rowA + 1;
        Cm[rowA][tx * 4 + 0] = u0.x; Cm[rowA][tx * 4 + 1] = u1.x;
        Cm[rowA][tx * 4 + 2] = u2.x; Cm[rowA][tx * 4 + 3] = u3.x;
        Cm[rowB][tx * 4 + 0] = u0.y; Cm[rowB][tx * 4 + 1] = u1.y;
        Cm[rowB][tx * 4 + 2] = u2.y; Cm[rowB][tx * 4 + 3] = u3.y;
    }
}

__global__ void __launch_bounds__(256) solve_kernel() {
    extern __shared__ float sm[];
    float (*An)[68] = (float(*)[68])sm;
    float (*Z)[68]  = (float(*)[68])(sm + 1 * 64 * 68);
    float (*B1)[68] = (float(*)[68])(sm + 2 * 64 * 68);
    float (*B2)[68] = (float(*)[68])(sm + 3 * 64 * 68);
    __shared__ float rowsum[64];
    __shared__ float rinv;

    const int tid = threadIdx.x;
    const int ty = tid >> 4, tx = tid & 15;
    const float invm = 1.f / (float)MTOT;

    for (int e = tid; e < 4096; e += 256) {
        const int i = e >> 6, j = e & 63;
        float s = g_G[e] * invm - (g_S[i] * invm) * (g_S[j] * invm);
        if (i == j) s += EPSV;
        An[i][j] = s;
        Z[i][j] = (i == j) ? 1.f : 0.f;
    }
    __syncthreads();
    if (tid < 64) {
        float rs = 0.f;
        for (int j = 0; j < 64; ++j) rs += fabsf(An[tid][j]);
        rowsum[tid] = rs;
    }
    __syncthreads();
    if (tid == 0) {
        float mx = 0.f;
        for (int i = 0; i < 64; ++i) mx = fmaxf(mx, rowsum[i]);
        rinv = 1.f / mx;
    }
    __syncthreads();
    const float r = rinv;
    for (int e = tid; e < 4096; e += 256) An[e >> 6][e & 63] *= r;
    __syncthreads();

    for (int it = 0; it < NS_ITERS; ++it) {
        mm64_2(Z, Z, B1, ty, tx);     // B1 = Z^2
        __syncthreads();
        mm64_2(B1, Z, B2, ty, tx);    // B2 = Z^3
        __syncthreads();
        {   // Z = 1.5 Z - 0.5 * An * B2
            uint64_t acc[2][4];
#pragma unroll
            for (int i = 0; i < 2; ++i)
#pragma unroll
                for (int j = 0; j < 4; ++j) acc[i][j] = 0ull;
#pragma unroll 8
            for (int k = 0; k < 64; ++k) {
                const ulonglong2 a = *reinterpret_cast<const ulonglong2*>(&An[k][ty * 4]);
                const float4 b = *reinterpret_cast<const float4*>(&B2[k][tx * 4]);
                const uint64_t bd[4] = {pack2(b.x), pack2(b.y), pack2(b.z), pack2(b.w)};
#pragma unroll
                for (int j = 0; j < 4; ++j) { ffma2(acc[0][j], a.x, bd[j]); ffma2(acc[1][j], a.y, bd[j]); }
            }
#pragma unroll
            for (int i = 0; i < 2; ++i) {
                const float2 u[4] = {unpack2(acc[i][0]), unpack2(acc[i][1]),
                                     unpack2(acc[i][2]), unpack2(acc[i][3])};
                const int rowA = ty * 4 + 2 * i, rowB = rowA + 1;
#pragma unroll
                for (int j = 0; j < 4; ++j) {
                    Z[rowA][tx * 4 + j] = 1.5f * Z[rowA][tx * 4 + j] - 0.5f * u[j].x;
                    Z[rowB][tx * 4 + j] = 1.5f * Z[rowB][tx * 4 + j] - 0.5f * u[j].y;
                }
            }
        }
        __syncthreads();
    }

    const float sr = sqrtf(r);
    for (int e = tid; e < 4096; e += 256) g_wm[e] = Z[e >> 6][e & 63] * sr;
    __syncthreads();
    if (tid < 64) {
        float b = 0.f;
        for (int k = 0; k < 64; ++k) b += Z[tid][k] * g_S[k];
        g_bias[tid] = b * sr * invm;   // wm @ mean
    }
}

// =====================================================================
// Pass 3: apply. 128 threads, 8x4 tile, cp.async 2-stage pipeline.
// =====================================================================
__device__ __forceinline__ void apply_issue(const float* __restrict__ X, int tile,
                                            float (*buf)[68], int tid) {
    const int n = tile / STILES;
    const int s0 = (tile - n * STILES) * 64;
#pragma unroll
    for (int r = 0; r < 8; ++r) {
        const int idx = tid + r * 128;
        const int c = idx >> 4, p = (idx & 15) << 2;
        cpasync16((uint32_t)__cvta_generic_to_shared(&buf[c][p]),
                  X + (size_t)(n * C64 + c) * HW + s0 + p);
    }
    cp_commit();
}

__global__ void __launch_bounds__(128) apply_kernel(const float* __restrict__ X,
                                                    float* __restrict__ Y) {
    extern __shared__ float sm[];
    float (*Wm)[68]  = (float(*)[68])sm;
    float (*Xs0)[68] = (float(*)[68])(sm + 4352);
    float (*Xs1)[68] = (float(*)[68])(sm + 2 * 4352);
    float* bs = sm + 3 * 4352;

    const int tid = threadIdx.x;
    const int ty = tid >> 4, tx = tid & 15;

    const float4* gw = reinterpret_cast<const float4*>(g_wm);
#pragma unroll
    for (int i = 0; i < 8; ++i) {
        const int idx4 = tid + i * 128;            // 0..1023
        const int rr = idx4 >> 4, cc = (idx4 & 15) << 2;
        *reinterpret_cast<float4*>(&Wm[rr][cc]) = gw[idx4];
    }
    if (tid < 64) bs[tid] = g_bias[tid];

    const int tile0 = blockIdx.x * TPB2;
    apply_issue(X, tile0 + 0, Xs0, tid);
    apply_issue(X, tile0 + 1, Xs1, tid);

#pragma unroll 1
    for (int t = 0; t < TPB2; ++t) {
        cp_wait1();
        __syncthreads();
        float (*Xb)[68] = (t & 1) ? Xs1 : Xs0;

        uint64_t acc[4][4];
#pragma unroll
        for (int i = 0; i < 4; ++i)
#pragma unroll
            for (int j = 0; j < 4; ++j) acc[i][j] = 0ull;
        // out[c][s] = sum_k wm[c][k] x[k][s]; wm symmetric -> Wm[k][c]
        gemm_acc2(Wm, Xb, acc, ty, tx);

        const int tile = tile0 + t;
        const int n = tile / STILES;
        const int s0 = (tile - n * STILES) * 64;
#pragma unroll
        for (int i = 0; i < 4; ++i) {
            const float2 u0 = unpack2(acc[i][0]);
            const float2 u1 = unpack2(acc[i][1]);
            const float2 u2 = unpack2(acc[i][2]);
            const float2 u3 = unpack2(acc[i][3]);
            const int cA = ty * 8 + 2 * i, cB = cA + 1;
            const float bA = bs[cA], bB = bs[cB];
            *reinterpret_cast<float4*>(Y + (size_t)(n * C64 + cA) * HW + s0 + tx * 4) =
                make_float4(u0.x - bA, u1.x - bA, u2.x - bA, u3.x - bA);
            *reinterpret_cast<float4*>(Y + (size_t)(n * C64 + cB) * HW + s0 + tx * 4) =
                make_float4(u0.y - bB, u1.y - bB, u2.y - bB, u3.y - bB);
        }
        __syncthreads();
        if (t + 2 < TPB2) apply_issue(X, tile0 + t + 2, Xb, tid);
        else cp_commit();   // empty group keeps wait_group<1> semantics valid
    }
}

// =====================================================================
extern "C" void kernel_launch(void* const* d_in, const int* in_sizes, int n_in,
                              void* d_out, int out_size) {
    const float* X = (const float*)d_in[0];
    float* Y = (float*)d_out;

    cudaFuncSetAttribute(solve_kernel, cudaFuncAttributeMaxDynamicSharedMemorySize,
                         4 * 64 * 68 * (int)sizeof(float));
    cudaFuncSetAttribute(apply_kernel, cudaFuncAttributeMaxDynamicSharedMemorySize,
                         (3 * 4352 + 64) * (int)sizeof(float));

    gram_kernel<<<NB1, 128>>>(X);
    reduce_kernel<<<129, 128>>>();
    solve_kernel<<<1, 256, 4 * 64 * 68 * sizeof(float)>>>();
    apply_kernel<<<NB2, 128, (3 * 4352 + 64) * sizeof(float)>>>(X, Y);
}

// round 6
// speedup vs baseline: 1.9064x; 1.5498x over previous
#include <cuda_runtime.h>
#include <stdint.h>
#include <math.h>

#define C64 64
#define HW  3136
#define MTOT 401408            // 128*3136
#define PTILES 98              // 3136/32 position tiles per image
#define NBG 392
#define TPG 32                 // 392*32 = 12544 tiles
#define NBA 392
#define TPA 32
#define NS_ITERS 4
#define EPSV 1e-3f
#define GS 36                  // smem tile stride in floats (144B rows)

// -------- device scratch (no allocations allowed) --------
__device__ float g_partG[NBG][C64 * C64];
__device__ float g_partS[NBG][C64];
__device__ float g_G[C64 * C64];
__device__ float g_S[C64];
__device__ float g_wm[C64 * C64];
__device__ float g_bias[C64];

// =============================== helpers ===============================
__device__ __forceinline__ void cpasync16(uint32_t dst, const void* src) {
    asm volatile("cp.async.cg.shared.global [%0], [%1], 16;" :: "r"(dst), "l"(src));
}
__device__ __forceinline__ void cp_commit() {
    asm volatile("cp.async.commit_group;" ::: "memory");
}
__device__ __forceinline__ void cp_wait2() {
    asm volatile("cp.async.wait_group 2;" ::: "memory");
}

// m16n8k8 tf32 HMMA (sm_80+ feature, works on bare sm_103 target).
// HW truncates fp32 operands to tf32 internally.
__device__ __forceinline__ void mma_tf32(float* c, uint32_t a0, uint32_t a1,
                                         uint32_t a2, uint32_t a3,
                                         uint32_t b0, uint32_t b1) {
    asm volatile("mma.sync.aligned.m16n8k8.row.col.f32.tf32.tf32.f32 "
                 "{%0,%1,%2,%3}, {%4,%5,%6,%7}, {%8,%9}, {%0,%1,%2,%3};"
                 : "+f"(c[0]), "+f"(c[1]), "+f"(c[2]), "+f"(c[3])
                 : "r"(a0), "r"(a1), "r"(a2), "r"(a3), "r"(b0), "r"(b1));
}
__device__ __forceinline__ uint32_t ldf(const float* p) {
    return __float_as_uint(*p);
}

// tile cp.async: 64 rows x 32 f32 into [64][GS] smem; 256 thr x 2 chunks.
__device__ __forceinline__ void tile_issue(const float* __restrict__ X, int tile,
                                           float* stage, int tid) {
    const int n = tile / PTILES;
    const int s0 = (tile - n * PTILES) * 32;
    const float* base = X + (size_t)n * (C64 * HW) + s0;
    const uint32_t sa = (uint32_t)__cvta_generic_to_shared(stage);
#pragma unroll
    for (int j = 0; j < 2; ++j) {
        const int idx = tid + j * 256;
        const int r = idx >> 3, q = idx & 7;
        cpasync16(sa + (uint32_t)(r * GS * 4 + q * 16), base + (size_t)r * HW + 4 * q);
    }
    cp_commit();
}

// =====================================================================
// Pass 1: tf32 HMMA Gram. 256 thr / 8 warps; warp w owns rows (w&3)*16..+15,
// cols (w>>2)*32..+31 of G; accumulators persist across 32 tiles.
// =====================================================================
__global__ void __launch_bounds__(256) gram_kernel(const float* __restrict__ X) {
    __shared__ float stg[4][64 * GS];
    __shared__ float ssc[4][64];

    const int tid = threadIdx.x;
    const int wid = tid >> 5, lane = tid & 31;
    const int la2 = lane >> 2, la3 = lane & 3;
    const int rb = (wid & 3) * 16, cb = (wid >> 2) * 32;
    const int sch = tid & 63, seg = tid >> 6;

    float acc[4][4];
#pragma unroll
    for (int i = 0; i < 4; ++i)
#pragma unroll
        for (int j = 0; j < 4; ++j) acc[i][j] = 0.f;
    float ssum = 0.f;

    const int tile0 = blockIdx.x * TPG;
    tile_issue(X, tile0 + 0, stg[0], tid);
    tile_issue(X, tile0 + 1, stg[1], tid);
    tile_issue(X, tile0 + 2, stg[2], tid);

#pragma unroll 1
    for (int t = 0; t < TPG; ++t) {
        const float* S = stg[t & 3];
        cp_wait2();
        __syncthreads();

        // channel sums: thread reads 8 floats of its (ch, seg) strip
        {
            const float4 u = *reinterpret_cast<const float4*>(S + sch * GS + seg * 8);
            const float4 v = *reinterpret_cast<const float4*>(S + sch * GS + seg * 8 + 4);
            ssum += ((u.x + u.y) + (u.z + u.w)) + ((v.x + v.y) + (v.z + v.w));
        }

#pragma unroll
        for (int kk = 0; kk < 4; ++kk) {
            const int k0 = kk * 8;
            const uint32_t a0 = ldf(S + (rb + la2) * GS + k0 + la3);
            const uint32_t a1 = ldf(S + (rb + 8 + la2) * GS + k0 + la3);
            const uint32_t a2 = ldf(S + (rb + la2) * GS + k0 + 4 + la3);
            const uint32_t a3 = ldf(S + (rb + 8 + la2) * GS + k0 + 4 + la3);
#pragma unroll
            for (int nt = 0; nt < 4; ++nt) {
                const int n0 = cb + nt * 8;
                const uint32_t b0 = ldf(S + (n0 + la2) * GS + k0 + la3);
                const uint32_t b1 = ldf(S + (n0 + la2) * GS + k0 + 4 + la3);
                mma_tf32(acc[nt], a0, a1, a2, a3, b0, b1);
            }
        }

        if (t + 3 < TPG) tile_issue(X, tile0 + t + 3, stg[(t + 3) & 3], tid);
        else cp_commit();   // keep group accounting consistent
    }

    // write partial G
    float* pg = g_partG[blockIdx.x];
#pragma unroll
    for (int nt = 0; nt < 4; ++nt) {
        const int r0 = rb + la2, c0 = cb + nt * 8 + la3 * 2;
        *reinterpret_cast<float2*>(pg + r0 * C64 + c0) = make_float2(acc[nt][0], acc[nt][1]);
        *reinterpret_cast<float2*>(pg + (r0 + 8) * C64 + c0) = make_float2(acc[nt][2], acc[nt][3]);
    }
    // reduce channel sums
    ssc[seg][sch] = ssum;
    __syncthreads();
    if (tid < 64)
        g_partS[blockIdx.x][tid] = (ssc[0][tid] + ssc[1][tid]) + (ssc[2][tid] + ssc[3][tid]);
}

// =====================================================================
// Pass 1.5: reduce partials (fixed order -> deterministic)
// =====================================================================
__global__ void __launch_bounds__(128) reduce_kernel() {
    const int tid = threadIdx.x;
    if (blockIdx.x < 128) {
        __shared__ float4 s[8][8];
        if (tid < 64) {
            const int lane = tid & 7, g = tid >> 3;
            const int e4 = blockIdx.x * 8 + lane;
            const float4* pg = reinterpret_cast<const float4*>(g_partG);
            float4 a = make_float4(0.f, 0.f, 0.f, 0.f);
            const int b0 = g * (NBG / 8);
#pragma unroll 7
            for (int b = 0; b < NBG / 8; ++b) {
                const float4 t = pg[(size_t)(b0 + b) * 1024 + e4];
                a.x += t.x; a.y += t.y; a.z += t.z; a.w += t.w;
            }
            s[g][lane] = a;
        }
        __syncthreads();
        if (tid < 8) {
            float4 r = make_float4(0.f, 0.f, 0.f, 0.f);
            for (int i = 0; i < 8; ++i) {
                const float4 t = s[i][tid];
                r.x += t.x; r.y += t.y; r.z += t.z; r.w += t.w;
            }
            reinterpret_cast<float4*>(g_G)[blockIdx.x * 8 + tid] = r;
        }
    } else {
        __shared__ float s2[2][64];
        const int ch = tid & 63, half = tid >> 6;
        float a = 0.f;
        const int b0 = half * (NBG / 2);
#pragma unroll 4
        for (int b = 0; b < NBG / 2; ++b) a += g_partS[b0 + b][ch];
        s2[half][ch] = a;
        __syncthreads();
        if (tid < 64) g_S[tid] = s2[0][tid] + s2[1][tid];
    }
}

// =====================================================================
// Pass 2: single-block Newton-Schulz inverse sqrt (fp32, FFMA2), 256 thr
// =====================================================================
__device__ __forceinline__ uint64_t pack2(float v) {
    uint64_t r; asm("mov.b64 %0, {%1, %1};" : "=l"(r) : "f"(v)); return r;
}
__device__ __forceinline__ void ffma2(uint64_t& d, uint64_t a, uint64_t b) {
    asm("fma.rn.f32x2 %0, %1, %2, %0;" : "+l"(d) : "l"(a), "l"(b));
}
__device__ __forceinline__ float2 unpack2(uint64_t v) {
    float2 f; asm("mov.b64 {%0, %1}, %2;" : "=f"(f.x), "=f"(f.y) : "l"(v)); return f;
}

__device__ __forceinline__ void mm64_2(const float (*P)[68], const float (*Q)[68],
                                       float (*Cm)[68], int ty, int tx) {
    uint64_t acc[2][4];
#pragma unroll
    for (int i = 0; i < 2; ++i)
#pragma unroll
        for (int j = 0; j < 4; ++j) acc[i][j] = 0ull;
#pragma unroll 8
    for (int k = 0; k < 64; ++k) {
        const ulonglong2 a = *reinterpret_cast<const ulonglong2*>(&P[k][ty * 4]);
        const float4 b = *reinterpret_cast<const float4*>(&Q[k][tx * 4]);
        const uint64_t bd[4] = {pack2(b.x), pack2(b.y), pack2(b.z), pack2(b.w)};
#pragma unroll
        for (int j = 0; j < 4; ++j) { ffma2(acc[0][j], a.x, bd[j]); ffma2(acc[1][j], a.y, bd[j]); }
    }
#pragma unroll
    for (int i = 0; i < 2; ++i) {
        const float2 u0 = unpack2(acc[i][0]), u1 = unpack2(acc[i][1]);
        const float2 u2 = unpack2(acc[i][2]), u3 = unpack2(acc[i][3]);
        const int rowA = ty * 4 + 2 * i, rowB = rowA + 1;
        Cm[rowA][tx * 4 + 0] = u0.x; Cm[rowA][tx * 4 + 1] = u1.x;
        Cm[rowA][tx * 4 + 2] = u2.x; Cm[rowA][tx * 4 + 3] = u3.x;
        Cm[rowB][tx * 4 + 0] = u0.y; Cm[rowB][tx * 4 + 1] = u1.y;
        Cm[rowB][tx * 4 + 2] = u2.y; Cm[rowB][tx * 4 + 3] = u3.y;
    }
}

__global__ void __launch_bounds__(256) solve_kernel() {
    extern __shared__ float smf[];
    float (*An)[68] = (float(*)[68])smf;
    float (*Z)[68]  = (float(*)[68])(smf + 1 * 64 * 68);
    float (*B1)[68] = (float(*)[68])(smf + 2 * 64 * 68);
    float (*B2)[68] = (float(*)[68])(smf + 3 * 64 * 68);
    __shared__ float rowsum[64];
    __shared__ float rinv;

    const int tid = threadIdx.x;
    const int ty = tid >> 4, tx = tid & 15;
    const float invm = 1.f / (float)MTOT;

    for (int e = tid; e < 4096; e += 256) {
        const int i = e >> 6, j = e & 63;
        float s = g_G[e] * invm - (g_S[i] * invm) * (g_S[j] * invm);
        if (i == j) s += EPSV;
        An[i][j] = s;
        Z[i][j] = (i == j) ? 1.f : 0.f;
    }
    __syncthreads();
    if (tid < 64) {
        float rs = 0.f;
        for (int j = 0; j < 64; ++j) rs += fabsf(An[tid][j]);
        rowsum[tid] = rs;
    }
    __syncthreads();
    if (tid == 0) {
        float mx = 0.f;
        for (int i = 0; i < 64; ++i) mx = fmaxf(mx, rowsum[i]);
        rinv = 1.f / mx;
    }
    __syncthreads();
    const float r = rinv;
    for (int e = tid; e < 4096; e += 256) An[e >> 6][e & 63] *= r;
    __syncthreads();

    for (int it = 0; it < NS_ITERS; ++it) {
        mm64_2(Z, Z, B1, ty, tx);
        __syncthreads();
        mm64_2(B1, Z, B2, ty, tx);
        __syncthreads();
        {
            uint64_t acc[2][4];
#pragma unroll
            for (int i = 0; i < 2; ++i)
#pragma unroll
                for (int j = 0; j < 4; ++j) acc[i][j] = 0ull;
#pragma unroll 8
            for (int k = 0; k < 64; ++k) {
                const ulonglong2 a = *reinterpret_cast<const ulonglong2*>(&An[k][ty * 4]);
                const float4 b = *reinterpret_cast<const float4*>(&B2[k][tx * 4]);
                const uint64_t bd[4] = {pack2(b.x), pack2(b.y), pack2(b.z), pack2(b.w)};
#pragma unroll
                for (int j = 0; j < 4; ++j) { ffma2(acc[0][j], a.x, bd[j]); ffma2(acc[1][j], a.y, bd[j]); }
            }
#pragma unroll
            for (int i = 0; i < 2; ++i) {
                const float2 u[4] = {unpack2(acc[i][0]), unpack2(acc[i][1]),
                                     unpack2(acc[i][2]), unpack2(acc[i][3])};
                const int rowA = ty * 4 + 2 * i, rowB = rowA + 1;
#pragma unroll
                for (int j = 0; j < 4; ++j) {
                    Z[rowA][tx * 4 + j] = 1.5f * Z[rowA][tx * 4 + j] - 0.5f * u[j].x;
                    Z[rowB][tx * 4 + j] = 1.5f * Z[rowB][tx * 4 + j] - 0.5f * u[j].y;
                }
            }
        }
        __syncthreads();
    }

    const float sr = sqrtf(r);
    for (int e = tid; e < 4096; e += 256) g_wm[e] = Z[e >> 6][e & 63] * sr;
    __syncthreads();
    if (tid < 64) {
        float b = 0.f;
        for (int k = 0; k < 64; ++k) b += Z[tid][k] * g_S[k];
        g_bias[tid] = b * sr * invm;
    }
}

// =====================================================================
// Pass 3: tf32 HMMA apply. A = wm (smem row-major), B = X tiles.
// warp w owns rows (w&3)*16..+15, cols (w>>2)*16..+15 of each 64x32 tile.
// dynamic smem: Wm[64][68] | 4 stages [64][GS] | bias[64]
// =====================================================================
__global__ void __launch_bounds__(256) apply_kernel(const float* __restrict__ X,
                                                    float* __restrict__ Y) {
    extern __shared__ float sm[];
    float (*Wm)[68] = (float(*)[68])sm;                 // 64*68 = 4352 floats
    float* stages = sm + 4352;                          // 4 * 2304 floats
    float* bs = sm + 4352 + 4 * 64 * GS;

    const int tid = threadIdx.x;
    const int wid = tid >> 5, lane = tid & 31;
    const int la2 = lane >> 2, la3 = lane & 3;
    const int rb = (wid & 3) * 16, cbw = (wid >> 2) * 16;

    const float4* gw = reinterpret_cast<const float4*>(g_wm);
#pragma unroll
    for (int i = 0; i < 4; ++i) {
        const int idx4 = tid + i * 256;            // 0..1023
        const int rr = idx4 >> 4, cc = (idx4 & 15) << 2;
        *reinterpret_cast<float4*>(&Wm[rr][cc]) = gw[idx4];
    }
    if (tid < 64) bs[tid] = g_bias[tid];

    const int tile0 = blockIdx.x * TPA;
    tile_issue(X, tile0 + 0, stages + 0 * 64 * GS, tid);
    tile_issue(X, tile0 + 1, stages + 1 * 64 * GS, tid);
    tile_issue(X, tile0 + 2, stages + 2 * 64 * GS, tid);

    const float bA = 0.f;
    (void)bA;

#pragma unroll 1
    for (int t = 0; t < TPA; ++t) {
        const float* S = stages + (t & 3) * 64 * GS;
        cp_wait2();
        __syncthreads();

        float acc[2][4];
#pragma unroll
        for (int i = 0; i < 2; ++i)
#pragma unroll
            for (int j = 0; j < 4; ++j) acc[i][j] = 0.f;

#pragma unroll
        for (int kk = 0; kk < 8; ++kk) {
            const int k0 = kk * 8;
            const uint32_t a0 = __float_as_uint(Wm[rb + la2][k0 + la3]);
            const uint32_t a1 = __float_as_uint(Wm[rb + 8 + la2][k0 + la3]);
            const uint32_t a2 = __float_as_uint(Wm[rb + la2][k0 + 4 + la3]);
            const uint32_t a3 = __float_as_uint(Wm[rb + 8 + la2][k0 + 4 + la3]);
#pragma unroll
            for (int nt = 0; nt < 2; ++nt) {
                const int n0 = cbw + nt * 8;
                const uint32_t b0 = ldf(S + (k0 + la3) * GS + n0 + la2);
                const uint32_t b1 = ldf(S + (k0 + 4 + la3) * GS + n0 + la2);
                mma_tf32(acc[nt], a0, a1, a2, a3, b0, b1);
            }
        }

        const int tile = tile0 + t;
        const int n = tile / PTILES;
        const int s0 = (tile - n * PTILES) * 32;
        const int r0 = rb + la2;
        const float b0v = bs[r0], b1v = bs[r0 + 8];
#pragma unroll
        for (int nt = 0; nt < 2; ++nt) {
            const int c0 = cbw + nt * 8 + la3 * 2;
            *reinterpret_cast<float2*>(Y + (size_t)(n * C64 + r0) * HW + s0 + c0) =
                make_float2(acc[nt][0] - b0v, acc[nt][1] - b0v);
            *reinterpret_cast<float2*>(Y + (size_t)(n * C64 + r0 + 8) * HW + s0 + c0) =
                make_float2(acc[nt][2] - b1v, acc[nt][3] - b1v);
        }

        if (t + 3 < TPA) tile_issue(X, tile0 + t + 3, stages + ((t + 3) & 3) * 64 * GS, tid);
        else cp_commit();
    }
}

// =====================================================================
extern "C" void kernel_launch(void* const* d_in, const int* in_sizes, int n_in,
                              void* d_out, int out_size) {
    const float* X = (const float*)d_in[0];
    float* Y = (float*)d_out;

    const int apply_smem = (4352 + 4 * 64 * GS + 64) * (int)sizeof(float);
    cudaFuncSetAttribute(apply_kernel, cudaFuncAttributeMaxDynamicSharedMemorySize, apply_smem);
    cudaFuncSetAttribute(solve_kernel, cudaFuncAttributeMaxDynamicSharedMemorySize,
                         4 * 64 * 68 * (int)sizeof(float));

    gram_kernel<<<NBG, 256>>>(X);
    reduce_kernel<<<129, 128>>>();
    solve_kernel<<<1, 256, 4 * 64 * 68 * sizeof(float)>>>();
    apply_kernel<<<NBA, 256, apply_smem>>>(X, Y);
}